// round 9
// baseline (speedup 1.0000x reference)
#include <cuda_runtime.h>

#define Lf 512
#define Bf 4096
#define Tt 25
#define NP 13      // i-pairs (2p, 2p+1); slot p=12 hi half = pad (i=25)
#define GST 32     // g_score row stride (128B-aligned rows)
#define WPB 2      // warps per block in fwd kernel

__device__ float g_score[(size_t)Lf * Bf * GST];
__device__ float g_logz[Bf];
__device__ float g_num[Bf];

typedef unsigned long long u64;

__device__ __forceinline__ u64 pack2(float lo, float hi) {
    u64 r; asm("mov.b64 %0,{%1,%2};" : "=l"(r) : "f"(lo), "f"(hi)); return r;
}
__device__ __forceinline__ void un2(u64 v, float& a, float& b) {
    asm("mov.b64 {%0,%1},%2;" : "=f"(a), "=f"(b) : "l"(v));
}
__device__ __forceinline__ u64 fma2(u64 a, u64 b, u64 c) {
    u64 d; asm("fma.rn.f32x2 %0,%1,%2,%3;" : "=l"(d) : "l"(a), "l"(b), "l"(c)); return d;
}
__device__ __forceinline__ u64 add2(u64 a, u64 b) {
    u64 d; asm("add.rn.f32x2 %0,%1,%2;" : "=l"(d) : "l"(a), "l"(b)); return d;
}
__device__ __forceinline__ unsigned ford(float f) {
    unsigned v = __float_as_uint(f);
    return (v & 0x80000000u) ? ~v : (v | 0x80000000u);
}
__device__ __forceinline__ float rcpa(float x) {
    float r; asm("rcp.approx.f32 %0, %1;" : "=f"(r) : "f"(x)); return r;
}
__device__ __forceinline__ unsigned smem_u32(const void* p) {
    unsigned a;
    asm("{ .reg .u64 t; cvta.to.shared.u64 t, %1; cvt.u32.u64 %0, t; }"
        : "=r"(a) : "l"(p));
    return a;
}
__device__ __forceinline__ void sts32(unsigned addr, float v) {
    asm volatile("st.shared.b32 [%0], %1;" :: "r"(addr), "f"(v) : "memory");
}
__device__ __forceinline__ void lds_v2u64(unsigned addr, u64& x, u64& y) {
    asm volatile("ld.shared.v2.u64 {%0,%1}, [%2];"
                 : "=l"(x), "=l"(y) : "r"(addr) : "memory");
}

// ---------------------------------------------------------------------------
__global__ void init_kernel(float* out, int base) {
    int i = blockIdx.x * blockDim.x + threadIdx.x;
    if (i < Bf) g_num[i] = 0.f;
    if (i == 0 && base > 0) out[0] = 0.f;
}

// ---------------------------------------------------------------------------
// One fused forward+Viterbi step for both chains of this warp.
// Reads packed state {a-pair, v-pair} from smem buffer at ldA/ldB,
// publishes this thread's (a,v) there first (same-warp LSU order, convergent).
__device__ __forceinline__ void fwd_step(
    unsigned stA, unsigned stB, unsigned ldA, unsigned ldB,
    const u64* Ep, const u64* Tp,
    float& aA, float& vA, float& aB, float& vB,
    float& invA, float& invB,
    float eenA, float eenB, float enA, float enB,
    float& logaccA, float& logaccB,
    bool act, float*& gspA, float*& gspB)
{
    // publish state of previous step
    sts32(stA, aA); sts32(stA + 8, vA);
    sts32(stB, aB); sts32(stB + 8, vB);

    u64 rAe = 0ull, rAo = 0ull, rBe = 0ull, rBo = 0ull;
    float mA0 = -1e30f, mA1 = -1e30f, mA2 = -1e30f, mA3 = -1e30f;
    float mB0 = -1e30f, mB1 = -1e30f, mB2 = -1e30f, mB3 = -1e30f;
#pragma unroll
    for (int p = 0; p < NP; p++) {
        u64 avA, vvA, avB, vvB;
        lds_v2u64(ldA + p * 16, avA, vvA);
        lds_v2u64(ldB + p * 16, avB, vvB);
        float sx, sy;
        if (p & 1) {
            rAo = fma2(avA, Ep[p], rAo);
            rBo = fma2(avB, Ep[p], rBo);
            un2(add2(vvA, Tp[p]), sx, sy);
            mA2 = fmaxf(mA2, sx); mA3 = fmaxf(mA3, sy);
            un2(add2(vvB, Tp[p]), sx, sy);
            mB2 = fmaxf(mB2, sx); mB3 = fmaxf(mB3, sy);
        } else {
            rAe = fma2(avA, Ep[p], rAe);
            rBe = fma2(avB, Ep[p], rBe);
            un2(add2(vvA, Tp[p]), sx, sy);
            mA0 = fmaxf(mA0, sx); mA1 = fmaxf(mA1, sy);
            un2(add2(vvB, Tp[p]), sx, sy);
            mB0 = fmaxf(mB0, sx); mB1 = fmaxf(mB1, sy);
        }
    }
    float rx, ry;
    un2(add2(rAe, rAo), rx, ry);
    float uA = (rx + ry) * eenA * invA;
    un2(add2(rBe, rBo), rx, ry);
    float uB = (rx + ry) * eenB * invB;
    float svA = fmaxf(fmaxf(mA0, mA1), fmaxf(mA2, mA3)) + enA;  // exact: monotone
    float svB = fmaxf(fmaxf(mB0, mB1), fmaxf(mB2, mB3)) + enB;

    // log of applied scale (uniform value in every lane -> consistent exactly)
    logaccA -= __logf(invA);
    logaccB -= __logf(invB);

    aA = act ? uA : 0.f;   vA = act ? svA : -1e30f;
    aB = act ? uB : 0.f;   vB = act ? svB : -1e30f;
    if (act) { *gspA = svA; *gspB = svB; }
    gspA += (size_t)Bf * GST; gspB += (size_t)Bf * GST;

    // scale for NEXT step: lane 0's new alpha_0 (off critical path)
    invA = __shfl_sync(0xffffffffu, rcpa(uA), 0);
    invB = __shfl_sync(0xffffffffu, rcpa(uB), 0);
}

// Fused forward + Viterbi: 2 chains per warp, 64-thread blocks (grid 1024 ->
// balanced 14 warps/SM). No syncwarp: convergent warp, volatile smem asm.
__global__ __launch_bounds__(64, 7) void fwd_vit_kernel(
    const float* __restrict__ em, const float* __restrict__ trans,
    const float* __restrict__ start, const float* __restrict__ endt)
{
    // [buf][warp][chain][slot 0..15][4 floats {a_lo,a_hi,v_lo,v_hi}]
    __shared__ __align__(16) float sst[2][WPB][2][16][4];

    const int lane = threadIdx.x & 31;
    const int wl   = threadIdx.x >> 5;
    const int w    = blockIdx.x * WPB + wl;            // 0..2047
    const int bA   = w;
    const int bB   = w + Bf / 2;
    const bool act = lane < Tt;
    const int  j   = act ? lane : 0;
    const int  sp  = lane >> 1;
    const int  sh  = lane & 1;

    const unsigned base = smem_u32(&sst[0][0][0][0][0]);
    // region(buf, ch) = ((buf*WPB + wl)*2 + ch) * 256
    unsigned ldA0 = base + ((0 * WPB + wl) * 2 + 0) * 256;
    unsigned ldB0 = ldA0 + 256;
    unsigned ldA1 = base + ((1 * WPB + wl) * 2 + 0) * 256;
    unsigned ldB1 = ldA1 + 256;
    unsigned stA0 = ldA0 + sp * 16 + sh * 4;
    unsigned stB0 = ldB0 + sp * 16 + sh * 4;
    unsigned stA1 = ldA1 + sp * 16 + sh * 4;
    unsigned stB1 = ldB1 + sp * 16 + sh * 4;

    // loop-invariant tables
    u64 Ep[NP], Tp[NP];
#pragma unroll
    for (int p = 0; p < NP; p++) {
        const int i0 = 2 * p, i1 = 2 * p + 1;
        float t0 = trans[i0 * Tt + j];
        float t1 = (i1 < Tt) ? trans[i1 * Tt + j] : -1e30f;
        Tp[p] = pack2(t0, t1);
        Ep[p] = pack2(__expf(t0), (i1 < Tt) ? __expf(t1) : 0.f);
    }

    // ---- l = 0 state + emission pipeline ----
    const size_t emstep = (size_t)Bf * Tt;
    const float* empA = em + (size_t)bA * Tt + j;
    const float* empB = em + (size_t)bB * Tt + j;
    float e0A = *empA, e0B = *empB;            // em[0]
    empA += emstep; empB += emstep;
    float enA_cur = *empA, enB_cur = *empB;    // em[1]
    empA += emstep; empB += emstep;
    float enA_nxt = *empA, enB_nxt = *empB;    // em[2]
    empA += emstep; empB += emstep;            // -> em[3]

    const float stj = start[j];
    float s0A = stj + e0A, s0B = stj + e0B;
    float aA = act ? __expf(s0A) : 0.f;
    float vA = act ? s0A : -1e30f;
    float aB = act ? __expf(s0B) : 0.f;
    float vB = act ? s0B : -1e30f;

    float* gspA = &g_score[(size_t)bA * GST + j];
    float* gspB = &g_score[(size_t)bB * GST + j];
    if (act) { *gspA = s0A; *gspB = s0B; }
    gspA += (size_t)Bf * GST; gspB += (size_t)Bf * GST;

    float invA = __shfl_sync(0xffffffffu, rcpa(aA), 0);
    float invB = __shfl_sync(0xffffffffu, rcpa(aB), 0);
    float eenA = __expf(enA_cur);
    float eenB = __expf(enB_cur);
    float logaccA = 0.f, logaccB = 0.f;

    // ---- main loop, unrolled x2 over the double buffer ----
    for (int l = 1; l + 1 < Lf; l += 2) {
        // step l: buffer 0
        fwd_step(stA0, stB0, ldA0, ldB0, Ep, Tp, aA, vA, aB, vB,
                 invA, invB, eenA, eenB, enA_cur, enB_cur,
                 logaccA, logaccB, act, gspA, gspB);
        eenA = __expf(enA_nxt); eenB = __expf(enB_nxt);
        enA_cur = enA_nxt; enB_cur = enB_nxt;
        if (l + 2 < Lf) {
            enA_nxt = *empA; empA += emstep;
            enB_nxt = *empB; empB += emstep;
        }
        // step l+1: buffer 1
        fwd_step(stA1, stB1, ldA1, ldB1, Ep, Tp, aA, vA, aB, vB,
                 invA, invB, eenA, eenB, enA_cur, enB_cur,
                 logaccA, logaccB, act, gspA, gspB);
        eenA = __expf(enA_nxt); eenB = __expf(enB_nxt);
        enA_cur = enA_nxt; enB_cur = enB_nxt;
        if (l + 3 < Lf) {
            enA_nxt = *empA; empA += emstep;
            enB_nxt = *empB; empB += emstep;
        }
    }
    // final step l = 511 (buffer 0)
    fwd_step(stA0, stB0, ldA0, ldB0, Ep, Tp, aA, vA, aB, vB,
             invA, invB, eenA, eenB, enA_cur, enB_cur,
             logaccA, logaccB, act, gspA, gspB);

    // logz = logacc + log( sum_i a_final[i] * exp(end[i]) )
    float ee = __expf(endt[j]);
    float dA = act ? aA * ee : 0.f;
    float dB = act ? aB * ee : 0.f;
#pragma unroll
    for (int off = 16; off; off >>= 1) {
        dA += __shfl_xor_sync(0xffffffffu, dA, off);
        dB += __shfl_xor_sync(0xffffffffu, dB, off);
    }
    if (lane == 0) {
        g_logz[bA] = logaccA + __logf(dA);
        g_logz[bB] = logaccB + __logf(dB);
    }
}

// ---------------------------------------------------------------------------
__global__ void numer_kernel(const float* __restrict__ em, const int* __restrict__ tags,
                             const float* __restrict__ trans, const float* __restrict__ start,
                             const float* __restrict__ endt)
{
    int idx = blockIdx.x * blockDim.x + threadIdx.x;
    if (idx >= Bf * 32) return;
    int b  = idx & (Bf - 1);
    int c  = idx >> 12;
    int l0 = c * 16;
    float acc = 0.f;
    int prev = 0;
    if (c > 0) prev = tags[(size_t)(l0 - 1) * Bf + b];
#pragma unroll
    for (int dl = 0; dl < 16; dl++) {
        int l  = l0 + dl;
        int tg = tags[(size_t)l * Bf + b];
        acc += em[((size_t)l * Bf + b) * Tt + tg];
        if (l == 0) acc += start[tg];
        else        acc += trans[prev * Tt + tg];
        prev = tg;
    }
    if (l0 + 16 == Lf) acc += endt[prev];
    atomicAdd(&g_num[b], acc);
}

// ---------------------------------------------------------------------------
__device__ __forceinline__ void bt_group(
    const float* __restrict__ em, const float* st, float* out, int base,
    int b, int lane, bool alive, int lbase, int& jn,
    float (&cs)[8], float (&ce)[8], float (&ns)[8], float (&ne)[8], bool load_next)
{
    if (load_next) {
#pragma unroll
        for (int k = 0; k < 8; k++) {
            int l = lbase - 8 - k;
            bool ok = alive && (l >= 0);
            ns[k] = ok ? g_score[((size_t)l * Bf + b) * GST + lane] : 0.f;
            ne[k] = ok ? em[((size_t)(l + 1) * Bf + b) * Tt + lane] : 0.f;
        }
    }
#pragma unroll
    for (int k = 0; k < 8; k++) {
        int l = lbase - k;
        float ej = __shfl_sync(0xffffffffu, ce[k], jn);
        float tt = alive ? (cs[k] + st[lane * Tt + jn]) + ej : -3e38f;
        unsigned uu = ford(tt);
        unsigned mx = __reduce_max_sync(0xffffffffu, uu);
        int j2 = __ffs(__ballot_sync(0xffffffffu, uu == mx)) - 1;
        if (l >= 0) {
            jn = j2;
            if (lane == 0) out[base + (size_t)l * Bf + b] = (float)jn;
        }
    }
}

__global__ __launch_bounds__(256) void backtrack_kernel(
    const float* __restrict__ em, const float* __restrict__ trans,
    const float* __restrict__ endt, float* __restrict__ out, int base)
{
    __shared__ float st[Tt * Tt];
    __shared__ float cpart[8];
    const int tid = threadIdx.x;
    for (int i = tid; i < Tt * Tt; i += 256) st[i] = trans[i];
    __syncthreads();

    const int b    = (blockIdx.x * 256 + tid) >> 5;
    const int lane = tid & 31;
    const bool alive = lane < Tt;

    float sc = alive ? g_score[((size_t)(Lf - 1) * Bf + b) * GST + lane] : -3e38f;
    float t  = alive ? sc + endt[lane] : -3e38f;
    unsigned u  = ford(t);
    unsigned um = __reduce_max_sync(0xffffffffu, u);
    int jn = __ffs(__ballot_sync(0xffffffffu, u == um)) - 1;
    if (lane == 0) out[base + (size_t)(Lf - 1) * Bf + b] = (float)jn;

    float sA[8], eA[8], sB[8], eB[8];
#pragma unroll
    for (int k = 0; k < 8; k++) {
        int l = Lf - 2 - k;
        sA[k] = alive ? g_score[((size_t)l * Bf + b) * GST + lane] : 0.f;
        eA[k] = alive ? em[((size_t)(l + 1) * Bf + b) * Tt + lane] : 0.f;
    }
    for (int g = 0; g < 64; g += 2) {
        bt_group(em, st, out, base, b, lane, alive, Lf - 2 - 8 * g, jn,
                 sA, eA, sB, eB, true);
        bt_group(em, st, out, base, b, lane, alive, Lf - 2 - 8 * (g + 1), jn,
                 sB, eB, sA, eA, g + 1 < 63);
    }

    float c = 0.f;
    if (lane == 0 && base > 0) c = (g_logz[b] - g_num[b]) * (1.0f / Bf);
    if (lane == 0) cpart[tid >> 5] = c;
    __syncthreads();
    if (tid == 0 && base > 0) {
        float sum = 0.f;
#pragma unroll
        for (int w = 0; w < 8; w++) sum += cpart[w];
        atomicAdd(out, sum);
    }
}

// ---------------------------------------------------------------------------
extern "C" void kernel_launch(void* const* d_in, const int* in_sizes, int n_in,
                              void* d_out, int out_size) {
    const float* em    = (const float*)d_in[0];
    const int*   tags  = (const int*)d_in[1];
    const float* trans = (const float*)d_in[2];
    const float* start = (const float*)d_in[3];
    const float* endt  = (const float*)d_in[4];
    float* out = (float*)d_out;

    int base = out_size - Lf * Bf;
    if (base < 0) base = 0;

    init_kernel<<<16, 256>>>(out, base);
    fwd_vit_kernel<<<Bf / (2 * WPB), 32 * WPB>>>(em, trans, start, endt); // 1024 x 64
    numer_kernel<<<(Bf * 32) / 256, 256>>>(em, tags, trans, start, endt);
    backtrack_kernel<<<(Bf * 32) / 256, 256>>>(em, trans, endt, out, base);
}